// round 15
// baseline (speedup 1.0000x reference)
#include <cuda_runtime.h>
#include <cstdint>

#define B_  4
#define S_  2048
#define D_  1024
#define H_  16
#define DK_ 64
#define DV_ 64

// ---------------------------------------------------------------------------
// Scratch (device globals; no allocation allowed in kernel_launch)
// ---------------------------------------------------------------------------
__device__ float g_q [B_*S_*H_*DK_];   // [b,s,h,k]
__device__ float g_k [B_*S_*H_*DK_];
__device__ float g_v [B_*S_*H_*DV_];
__device__ float g_ao[B_*S_*H_*DV_];   // attention output [b,s,h,v]

// ---------------------------------------------------------------------------
// Helpers
// ---------------------------------------------------------------------------
__device__ __forceinline__ uint32_t smem_u32(const void* p) {
    uint32_t a;
    asm("{ .reg .u64 t; cvta.to.shared.u64 t, %1; cvt.u32.u64 %0, t; }" : "=r"(a) : "l"(p));
    return a;
}
__device__ __forceinline__ void ldsm_x4(uint32_t& r0, uint32_t& r1, uint32_t& r2, uint32_t& r3,
                                        uint32_t addr) {
    asm volatile("ldmatrix.sync.aligned.m8n8.x4.shared.b16 {%0,%1,%2,%3}, [%4];"
                 : "=r"(r0), "=r"(r1), "=r"(r2), "=r"(r3) : "r"(addr));
}
__device__ __forceinline__ void mma_tf32(float c[4],
                                         uint32_t a0, uint32_t a1, uint32_t a2, uint32_t a3,
                                         uint32_t b0, uint32_t b1) {
    asm volatile("mma.sync.aligned.m16n8k8.row.col.f32.tf32.tf32.f32 "
                 "{%0,%1,%2,%3},{%4,%5,%6,%7},{%8,%9},{%0,%1,%2,%3};"
                 : "+f"(c[0]), "+f"(c[1]), "+f"(c[2]), "+f"(c[3])
                 : "r"(a0), "r"(a1), "r"(a2), "r"(a3), "r"(b0), "r"(b1));
}
__device__ __forceinline__ uint32_t f2tf32(float x) {
    uint32_t r;
    asm("cvt.rna.tf32.f32 %0, %1;" : "=r"(r) : "f"(x));
    return r;
}
// swizzled smem byte address: rows of 64 f32 (16 chunks of 16B), chunk ^= row&7
__device__ __forceinline__ uint32_t swz(uint32_t base, int row, int ch) {
    return base + row * 256 + ((uint32_t)(ch ^ (row & 7)) << 4);
}

// ---------------------------------------------------------------------------
// HMMA tf32 GEMM:  C[M,N] = A[M,K] @ W[N,K]^T   (unchanged from R3, WIN)
// ---------------------------------------------------------------------------
#define GEMM_SMEM 65536

__global__ __launch_bounds__(256)
void gemm_hmma(const float* __restrict__ A, const float* __restrict__ W,
               float* __restrict__ C, int M, int N, int K)
{
    extern __shared__ __align__(128) float smem[];
    const uint32_t sbase = smem_u32(smem);
    const int tid  = threadIdx.x;
    const int lane = tid & 31;
    const int wid  = tid >> 5;
    const int wm   = wid & 1;
    const int wn   = wid >> 1;
    const int m0   = blockIdx.y * 128;
    const int n0   = blockIdx.x * 128;

    int lrow[4], lch[4];
    #pragma unroll
    for (int q = 0; q < 4; q++) { int id = tid + q * 256; lrow[q] = id >> 3; lch[q] = id & 7; }

    float c[4][4][4];
    #pragma unroll
    for (int mt = 0; mt < 4; mt++)
        #pragma unroll
        for (int nf = 0; nf < 4; nf++)
            #pragma unroll
            for (int r = 0; r < 4; r++) c[mt][nf][r] = 0.f;

    const float* Ab = A + (size_t)m0 * K;
    const float* Wb = W + (size_t)n0 * K;

    float4 stA[4], stW[4];
    #pragma unroll
    for (int q = 0; q < 4; q++) {
        stA[q] = *(const float4*)(Ab + (size_t)lrow[q] * K + lch[q] * 4);
        stW[q] = *(const float4*)(Wb + (size_t)lrow[q] * K + lch[q] * 4);
    }

    const int NIT = K / 32;

    #define STS_TILE(s_)                                                          \
        do {                                                                      \
            float* bufA = smem + (s_) * 8192;                                     \
            float* bufW = bufA + 4096;                                            \
            _Pragma("unroll")                                                     \
            for (int q = 0; q < 4; q++) {                                         \
                uint32_t off = lrow[q] * 32 + (lch[q] ^ (lrow[q] & 7)) * 4;       \
                float4 a = stA[q];                                                \
                *(float4*)(bufA + off) = make_float4(                             \
                    __uint_as_float(f2tf32(a.x)), __uint_as_float(f2tf32(a.y)),   \
                    __uint_as_float(f2tf32(a.z)), __uint_as_float(f2tf32(a.w)));  \
                float4 w = stW[q];                                                \
                *(float4*)(bufW + off) = make_float4(                             \
                    __uint_as_float(f2tf32(w.x)), __uint_as_float(f2tf32(w.y)),   \
                    __uint_as_float(f2tf32(w.z)), __uint_as_float(f2tf32(w.w)));  \
            }                                                                     \
        } while (0)

    STS_TILE(0);
    __syncthreads();

    for (int it = 0; it < NIT; it++) {
        const int s = it & 1;

        if (it + 1 < NIT) {
            const float* An = Ab + (it + 1) * 32;
            const float* Wn = Wb + (it + 1) * 32;
            #pragma unroll
            for (int q = 0; q < 4; q++) {
                stA[q] = *(const float4*)(An + (size_t)lrow[q] * K + lch[q] * 4);
                stW[q] = *(const float4*)(Wn + (size_t)lrow[q] * K + lch[q] * 4);
            }
        }

        const uint32_t bufA = sbase + s * 32768;
        const uint32_t bufW = bufA + 16384;

        #pragma unroll
        for (int ks = 0; ks < 4; ks++) {
            uint32_t a[4][4];
            #pragma unroll
            for (int mt = 0; mt < 4; mt++) {
                int row = wm * 64 + mt * 16 + (lane & 15);
                int ch  = (2 * ks + (lane >> 4)) ^ (row & 7);
                ldsm_x4(a[mt][0], a[mt][1], a[mt][2], a[mt][3],
                        bufA + row * 128 + ch * 16);
            }
            uint32_t b[4][2];
            #pragma unroll
            for (int p = 0; p < 2; p++) {
                int nrow = wn * 32 + p * 16 + (lane & 7) + ((lane >> 4) << 3);
                int ch   = (2 * ks + ((lane >> 3) & 1)) ^ (nrow & 7);
                uint32_t r0, r1, r2, r3;
                ldsm_x4(r0, r1, r2, r3, bufW + nrow * 128 + ch * 16);
                b[2*p][0] = r0; b[2*p][1] = r1;
                b[2*p+1][0] = r2; b[2*p+1][1] = r3;
            }
            #pragma unroll
            for (int mt = 0; mt < 4; mt++)
                #pragma unroll
                for (int nf = 0; nf < 4; nf++)
                    mma_tf32(c[mt][nf], a[mt][0], a[mt][1], a[mt][2], a[mt][3],
                             b[nf][0], b[nf][1]);
        }

        if (it + 1 < NIT) {
            STS_TILE((it + 1) & 1);
            __syncthreads();
        }
    }

    #pragma unroll
    for (int mt = 0; mt < 4; mt++) {
        int row = m0 + wm * 64 + mt * 16 + (lane >> 2);
        #pragma unroll
        for (int nf = 0; nf < 4; nf++) {
            int col = n0 + wn * 32 + nf * 8 + (lane & 3) * 2;
            *(float2*)(C + (size_t)row * N + col)       = make_float2(c[mt][nf][0], c[mt][nf][1]);
            *(float2*)(C + (size_t)(row + 8) * N + col) = make_float2(c[mt][nf][2], c[mt][nf][3]);
        }
    }
    #undef STS_TILE
}

// ---------------------------------------------------------------------------
// Flash attention on HMMA tf32.
// CTA: 128 q-rows, 8 warps (16 rows each, full 64-kv width -> warp-local softmax).
// grid = (S/128, H, B). smem: Qs 32KB | Ks 16KB | Vt 16KB | Ps 32KB = 96KB.
// ---------------------------------------------------------------------------
#define FLASH_SMEM 98304

__global__ __launch_bounds__(256, 2)
void flash_hmma(const float* __restrict__ Qg, const float* __restrict__ Kg,
                const float* __restrict__ Vg, const int* __restrict__ mask,
                float* __restrict__ O)
{
    extern __shared__ __align__(128) float sm[];
    const uint32_t sb = smem_u32(sm);
    const uint32_t QS = sb;
    const uint32_t KS = sb + 8192  * 4;
    const uint32_t VT = sb + 12288 * 4;
    const uint32_t PS = sb + 16384 * 4;

    const int tid  = threadIdx.x;
    const int lane = tid & 31;
    const int w    = tid >> 5;
    const int m0   = blockIdx.x * 128;
    const int h    = blockIdx.y;
    const int b    = blockIdx.z;

    // ---- load Q tile (scaled by 1/8, tf32-rounded), swizzled ----
    #pragma unroll
    for (int q = 0; q < 8; q++) {
        int id = tid + q * 256;
        int r  = id >> 4;
        int ch = id & 15;
        float4 v = *(const float4*)(Qg + ((size_t)(b*S_ + m0 + r) * H_ + h) * 64 + ch * 4);
        uint32_t x0 = f2tf32(v.x * 0.125f), x1 = f2tf32(v.y * 0.125f);
        uint32_t x2 = f2tf32(v.z * 0.125f), x3 = f2tf32(v.w * 0.125f);
        asm volatile("st.shared.v4.b32 [%0], {%1,%2,%3,%4};"
                     :: "r"(swz(QS, r, ch)), "r"(x0), "r"(x1), "r"(x2), "r"(x3) : "memory");
    }

    float o[8][4];
    #pragma unroll
    for (int nf = 0; nf < 8; nf++)
        #pragma unroll
        for (int e = 0; e < 4; e++) o[nf][e] = 0.f;
    float mi0 = -1e30f, mi1 = -1e30f, li0 = 0.f, li1 = 0.f;

    const int rl = lane >> 2;          // local row 0..7 (and +8)
    const int cb = (lane & 3) * 2;     // col pair base within n-frag

    for (int j0 = 0; j0 < S_; j0 += 64) {
        __syncthreads();
        // ---- load K (swizzled) and V (transposed, swizzled) ----
        #pragma unroll
        for (int q = 0; q < 4; q++) {
            int id = tid + q * 256;
            int t  = id & 63;
            int ch = id >> 6;          // 0..15
            size_t g = ((size_t)(b*S_ + j0 + t) * H_ + h) * 64 + ch * 4;
            float4 kv = *(const float4*)(Kg + g);
            uint32_t k0 = f2tf32(kv.x), k1 = f2tf32(kv.y), k2 = f2tf32(kv.z), k3 = f2tf32(kv.w);
            asm volatile("st.shared.v4.b32 [%0], {%1,%2,%3,%4};"
                         :: "r"(swz(KS, t, ch)), "r"(k0), "r"(k1), "r"(k2), "r"(k3) : "memory");
            float4 vv = *(const float4*)(Vg + g);
            uint32_t vr[4] = { f2tf32(vv.x), f2tf32(vv.y), f2tf32(vv.z), f2tf32(vv.w) };
            #pragma unroll
            for (int i = 0; i < 4; i++) {
                int vrow = ch * 4 + i;
                uint32_t ad = VT + vrow * 256 + ((uint32_t)((t >> 2) ^ (vrow & 7)) << 4)
                            + (t & 3) * 4;
                asm volatile("st.shared.b32 [%0], %1;" :: "r"(ad), "r"(vr[i]) : "memory");
            }
        }
        __syncthreads();

        // ---- scores: S = Q K^T  (16x64 per warp) ----
        float s[8][4];
        #pragma unroll
        for (int nf = 0; nf < 8; nf++)
            #pragma unroll
            for (int e = 0; e < 4; e++) s[nf][e] = 0.f;

        #pragma unroll
        for (int ks = 0; ks < 8; ks++) {
            uint32_t a0, a1, a2, a3;
            {
                int row = w * 16 + (lane & 7) + ((lane >> 3) & 1) * 8;
                int ch  = 2 * ks + (lane >> 4);
                ldsm_x4(a0, a1, a2, a3, swz(QS, row, ch));
            }
            #pragma unroll
            for (int i = 0; i < 4; i++) {
                int row = (lane & 7) + ((lane >> 4) << 3) + 16 * i;
                int ch  = 2 * ks + ((lane >> 3) & 1);
                uint32_t b0, b1, b2, b3;
                ldsm_x4(b0, b1, b2, b3, swz(KS, row, ch));
                mma_tf32(s[2*i],   a0, a1, a2, a3, b0, b1);
                mma_tf32(s[2*i+1], a0, a1, a2, a3, b2, b3);
            }
        }

        // ---- mask ----
        const int gr0 = m0 + w * 16 + rl;
        const int gr1 = gr0 + 8;
        #pragma unroll
        for (int nf = 0; nf < 8; nf++) {
            int col = j0 + nf * 8 + cb;
            int2 m0v = *(const int2*)(mask + ((size_t)b*S_ + gr0) * S_ + col);
            int2 m1v = *(const int2*)(mask + ((size_t)b*S_ + gr1) * S_ + col);
            if (m0v.x == 0) s[nf][0] = -1e10f;
            if (m0v.y == 0) s[nf][1] = -1e10f;
            if (m1v.x == 0) s[nf][2] = -1e10f;
            if (m1v.y == 0) s[nf][3] = -1e10f;
        }

        // ---- online softmax (warp-local; rows owned by quads) ----
        float mx0 = -1e30f, mx1 = -1e30f;
        #pragma unroll
        for (int nf = 0; nf < 8; nf++) {
            mx0 = fmaxf(mx0, fmaxf(s[nf][0], s[nf][1]));
            mx1 = fmaxf(mx1, fmaxf(s[nf][2], s[nf][3]));
        }
        #pragma unroll
        for (int off = 1; off <= 2; off <<= 1) {
            mx0 = fmaxf(mx0, __shfl_xor_sync(0xffffffffu, mx0, off));
            mx1 = fmaxf(mx1, __shfl_xor_sync(0xffffffffu, mx1, off));
        }
        float nm0 = fmaxf(mi0, mx0), nm1 = fmaxf(mi1, mx1);
        float c0 = __expf(mi0 - nm0), c1 = __expf(mi1 - nm1);
        mi0 = nm0; mi1 = nm1;

        float sum0 = 0.f, sum1 = 0.f;
        #pragma unroll
        for (int nf = 0; nf < 8; nf++) {
            s[nf][0] = __expf(s[nf][0] - nm0); sum0 += s[nf][0];
            s[nf][1] = __expf(s[nf][1] - nm0); sum0 += s[nf][1];
            s[nf][2] = __expf(s[nf][2] - nm1); sum1 += s[nf][2];
            s[nf][3] = __expf(s[nf][3] - nm1); sum1 += s[nf][3];
        }
        #pragma unroll
        for (int off = 1; off <= 2; off <<= 1) {
            sum0 += __shfl_xor_sync(0xffffffffu, sum0, off);
            sum1 += __shfl_xor_sync(0xffffffffu, sum1, off);
        }
        li0 = li0 * c0 + sum0;
        li1 = li1 * c1 + sum1;
        #pragma unroll
        for (int nf = 0; nf < 8; nf++) {
            o[nf][0] *= c0; o[nf][1] *= c0;
            o[nf][2] *= c1; o[nf][3] *= c1;
        }

        // ---- store P (tf32) to warp-private smem rows ----
        {
            const int pr0 = w * 16 + rl;
            const int pr8 = pr0 + 8;
            #pragma unroll
            for (int nf = 0; nf < 8; nf++) {
                int col   = nf * 8 + cb;
                int chunk = col >> 2;
                int cin   = (col & 3) * 4;
                uint32_t ad0 = PS + pr0 * 256 + ((uint32_t)(chunk ^ (pr0 & 7)) << 4) + cin;
                uint32_t ad1 = PS + pr8 * 256 + ((uint32_t)(chunk ^ (pr8 & 7)) << 4) + cin;
                uint32_t p0 = f2tf32(s[nf][0]), p1 = f2tf32(s[nf][1]);
                uint32_t p2 = f2tf32(s[nf][2]), p3 = f2tf32(s[nf][3]);
                asm volatile("st.shared.v2.b32 [%0], {%1,%2};" :: "r"(ad0), "r"(p0), "r"(p1) : "memory");
                asm volatile("st.shared.v2.b32 [%0], {%1,%2};" :: "r"(ad1), "r"(p2), "r"(p3) : "memory");
            }
        }
        __syncwarp();

        // ---- O += P @ V ----
        #pragma unroll
        for (int ks = 0; ks < 8; ks++) {
            uint32_t a0, a1, a2, a3;
            {
                int row = w * 16 + (lane & 7) + ((lane >> 3) & 1) * 8;
                int ch  = 2 * ks + (lane >> 4);
                ldsm_x4(a0, a1, a2, a3, swz(PS, row, ch));
            }
            #pragma unroll
            for (int i = 0; i < 4; i++) {
                int row = (lane & 7) + ((lane >> 4) << 3) + 16 * i;
                int ch  = 2 * ks + ((lane >> 3) & 1);
                uint32_t b0, b1, b2, b3;
                ldsm_x4(b0, b1, b2, b3, swz(VT, row, ch));
                mma_tf32(o[2*i],   a0, a1, a2, a3, b0, b1);
                mma_tf32(o[2*i+1], a0, a1, a2, a3, b2, b3);
            }
        }
    }

    // ---- epilogue ----
    {
        float i0 = 1.f / li0, i1 = 1.f / li1;
        const int gr0 = m0 + w * 16 + rl;
        const int gr1 = gr0 + 8;
        #pragma unroll
        for (int nf = 0; nf < 8; nf++) {
            int col = nf * 8 + cb;
            *(float2*)(O + ((size_t)(b*S_ + gr0) * H_ + h) * 64 + col)
                = make_float2(o[nf][0] * i0, o[nf][1] * i0);
            *(float2*)(O + ((size_t)(b*S_ + gr1) * H_ + h) * 64 + col)
                = make_float2(o[nf][2] * i1, o[nf][3] * i1);
        }
    }
}

// ---------------------------------------------------------------------------
// Launch
// ---------------------------------------------------------------------------
extern "C" void kernel_launch(void* const* d_in, const int* in_sizes, int n_in,
                              void* d_out, int out_size)
{
    const float* queries = (const float*)d_in[0];
    const float* keys    = (const float*)d_in[1];
    const float* values  = (const float*)d_in[2];
    const int*   mask    = (const int*  )d_in[3];
    const float* Wq      = (const float*)d_in[4];
    const float* Wk      = (const float*)d_in[5];
    const float* Wv      = (const float*)d_in[6];
    const float* Wo      = (const float*)d_in[7];
    float* out = (float*)d_out;

    float *q, *k, *v, *ao;
    cudaGetSymbolAddress((void**)&q,  g_q);
    cudaGetSymbolAddress((void**)&k,  g_k);
    cudaGetSymbolAddress((void**)&v,  g_v);
    cudaGetSymbolAddress((void**)&ao, g_ao);

    const int M = B_ * S_;        // 8192
    const int N = H_ * DK_;       // 1024

    cudaFuncSetAttribute(gemm_hmma, cudaFuncAttributeMaxDynamicSharedMemorySize, GEMM_SMEM);
    cudaFuncSetAttribute(flash_hmma, cudaFuncAttributeMaxDynamicSharedMemorySize, FLASH_SMEM);

    dim3 gg(N / 128, M / 128);    // (8, 64)
    gemm_hmma<<<gg, 256, GEMM_SMEM>>>(queries, Wq, q, M, N, D_);
    gemm_hmma<<<gg, 256, GEMM_SMEM>>>(keys,    Wk, k, M, N, D_);
    gemm_hmma<<<gg, 256, GEMM_SMEM>>>(values,  Wv, v, M, N, D_);

    dim3 gf(S_ / 128, H_, B_);    // (16, 16, 4)
    flash_hmma<<<gf, 256, FLASH_SMEM>>>(q, k, v, mask, ao);

    dim3 go(D_ / 128, M / 128);
    gemm_hmma<<<go, 256, GEMM_SMEM>>>(ao, Wo, out, M, D_, H_*DV_);
}

// round 16
// speedup vs baseline: 1.0048x; 1.0048x over previous
#include <cuda_runtime.h>
#include <cstdint>

#define B_  4
#define S_  2048
#define D_  1024
#define H_  16
#define DK_ 64
#define DV_ 64

// ---------------------------------------------------------------------------
// Scratch (device globals; no allocation allowed in kernel_launch)
// ---------------------------------------------------------------------------
__device__ float g_q [B_*S_*H_*DK_];   // [b,s,h,k]
__device__ float g_k [B_*S_*H_*DK_];
__device__ float g_v [B_*S_*H_*DV_];
__device__ float g_ao[B_*S_*H_*DV_];   // attention output [b,s,h,v]

// ---------------------------------------------------------------------------
// Helpers
// ---------------------------------------------------------------------------
__device__ __forceinline__ uint32_t smem_u32(const void* p) {
    uint32_t a;
    asm("{ .reg .u64 t; cvta.to.shared.u64 t, %1; cvt.u32.u64 %0, t; }" : "=r"(a) : "l"(p));
    return a;
}
__device__ __forceinline__ void ldsm_x4(uint32_t& r0, uint32_t& r1, uint32_t& r2, uint32_t& r3,
                                        uint32_t addr) {
    asm volatile("ldmatrix.sync.aligned.m8n8.x4.shared.b16 {%0,%1,%2,%3}, [%4];"
                 : "=r"(r0), "=r"(r1), "=r"(r2), "=r"(r3) : "r"(addr));
}
__device__ __forceinline__ void mma_tf32(float c[4],
                                         uint32_t a0, uint32_t a1, uint32_t a2, uint32_t a3,
                                         uint32_t b0, uint32_t b1) {
    asm volatile("mma.sync.aligned.m16n8k8.row.col.f32.tf32.tf32.f32 "
                 "{%0,%1,%2,%3},{%4,%5,%6,%7},{%8,%9},{%0,%1,%2,%3};"
                 : "+f"(c[0]), "+f"(c[1]), "+f"(c[2]), "+f"(c[3])
                 : "r"(a0), "r"(a1), "r"(a2), "r"(a3), "r"(b0), "r"(b1));
}
__device__ __forceinline__ uint32_t f2tf32(float x) {
    uint32_t r;
    asm("cvt.rna.tf32.f32 %0, %1;" : "=r"(r) : "f"(x));
    return r;
}
// swizzled smem byte address: rows of 64 f32 (16 chunks of 16B), chunk ^= row&7
__device__ __forceinline__ uint32_t swz(uint32_t base, int row, int ch) {
    return base + row * 256 + ((uint32_t)(ch ^ (row & 7)) << 4);
}

// ---------------------------------------------------------------------------
// HMMA tf32 GEMM:  C[M,N] = A[M,K] @ W[N,K]^T   (unchanged from R3, WIN)
// ---------------------------------------------------------------------------
#define GEMM_SMEM 65536

__global__ __launch_bounds__(256)
void gemm_hmma(const float* __restrict__ A, const float* __restrict__ W,
               float* __restrict__ C, int M, int N, int K)
{
    extern __shared__ __align__(128) float smem[];
    const uint32_t sbase = smem_u32(smem);
    const int tid  = threadIdx.x;
    const int lane = tid & 31;
    const int wid  = tid >> 5;
    const int wm   = wid & 1;
    const int wn   = wid >> 1;
    const int m0   = blockIdx.y * 128;
    const int n0   = blockIdx.x * 128;

    int lrow[4], lch[4];
    #pragma unroll
    for (int q = 0; q < 4; q++) { int id = tid + q * 256; lrow[q] = id >> 3; lch[q] = id & 7; }

    float c[4][4][4];
    #pragma unroll
    for (int mt = 0; mt < 4; mt++)
        #pragma unroll
        for (int nf = 0; nf < 4; nf++)
            #pragma unroll
            for (int r = 0; r < 4; r++) c[mt][nf][r] = 0.f;

    const float* Ab = A + (size_t)m0 * K;
    const float* Wb = W + (size_t)n0 * K;

    float4 stA[4], stW[4];
    #pragma unroll
    for (int q = 0; q < 4; q++) {
        stA[q] = *(const float4*)(Ab + (size_t)lrow[q] * K + lch[q] * 4);
        stW[q] = *(const float4*)(Wb + (size_t)lrow[q] * K + lch[q] * 4);
    }

    const int NIT = K / 32;

    #define STS_TILE(s_)                                                          \
        do {                                                                      \
            float* bufA = smem + (s_) * 8192;                                     \
            float* bufW = bufA + 4096;                                            \
            _Pragma("unroll")                                                     \
            for (int q = 0; q < 4; q++) {                                         \
                uint32_t off = lrow[q] * 32 + (lch[q] ^ (lrow[q] & 7)) * 4;       \
                float4 a = stA[q];                                                \
                *(float4*)(bufA + off) = make_float4(                             \
                    __uint_as_float(f2tf32(a.x)), __uint_as_float(f2tf32(a.y)),   \
                    __uint_as_float(f2tf32(a.z)), __uint_as_float(f2tf32(a.w)));  \
                float4 w = stW[q];                                                \
                *(float4*)(bufW + off) = make_float4(                             \
                    __uint_as_float(f2tf32(w.x)), __uint_as_float(f2tf32(w.y)),   \
                    __uint_as_float(f2tf32(w.z)), __uint_as_float(f2tf32(w.w)));  \
            }                                                                     \
        } while (0)

    STS_TILE(0);
    __syncthreads();

    for (int it = 0; it < NIT; it++) {
        const int s = it & 1;

        if (it + 1 < NIT) {
            const float* An = Ab + (it + 1) * 32;
            const float* Wn = Wb + (it + 1) * 32;
            #pragma unroll
            for (int q = 0; q < 4; q++) {
                stA[q] = *(const float4*)(An + (size_t)lrow[q] * K + lch[q] * 4);
                stW[q] = *(const float4*)(Wn + (size_t)lrow[q] * K + lch[q] * 4);
            }
        }

        const uint32_t bufA = sbase + s * 32768;
        const uint32_t bufW = bufA + 16384;

        #pragma unroll
        for (int ks = 0; ks < 4; ks++) {
            uint32_t a[4][4];
            #pragma unroll
            for (int mt = 0; mt < 4; mt++) {
                int row = wm * 64 + mt * 16 + (lane & 15);
                int ch  = (2 * ks + (lane >> 4)) ^ (row & 7);
                ldsm_x4(a[mt][0], a[mt][1], a[mt][2], a[mt][3],
                        bufA + row * 128 + ch * 16);
            }
            uint32_t b[4][2];
            #pragma unroll
            for (int p = 0; p < 2; p++) {
                int nrow = wn * 32 + p * 16 + (lane & 7) + ((lane >> 4) << 3);
                int ch   = (2 * ks + ((lane >> 3) & 1)) ^ (nrow & 7);
                uint32_t r0, r1, r2, r3;
                ldsm_x4(r0, r1, r2, r3, bufW + nrow * 128 + ch * 16);
                b[2*p][0] = r0; b[2*p][1] = r1;
                b[2*p+1][0] = r2; b[2*p+1][1] = r3;
            }
            #pragma unroll
            for (int mt = 0; mt < 4; mt++)
                #pragma unroll
                for (int nf = 0; nf < 4; nf++)
                    mma_tf32(c[mt][nf], a[mt][0], a[mt][1], a[mt][2], a[mt][3],
                             b[nf][0], b[nf][1]);
        }

        if (it + 1 < NIT) {
            STS_TILE((it + 1) & 1);
            __syncthreads();
        }
    }

    #pragma unroll
    for (int mt = 0; mt < 4; mt++) {
        int row = m0 + wm * 64 + mt * 16 + (lane >> 2);
        #pragma unroll
        for (int nf = 0; nf < 4; nf++) {
            int col = n0 + wn * 32 + nf * 8 + (lane & 3) * 2;
            *(float2*)(C + (size_t)row * N + col)       = make_float2(c[mt][nf][0], c[mt][nf][1]);
            *(float2*)(C + (size_t)(row + 8) * N + col) = make_float2(c[mt][nf][2], c[mt][nf][3]);
        }
    }
    #undef STS_TILE
}

// ---------------------------------------------------------------------------
// Flash attention on HMMA tf32.
// CTA: 128 q-rows, 8 warps (16 rows each, full 64-kv width -> warp-local softmax).
// grid = (S/128, H, B). smem: Qs 32KB | Ks 16KB | Vt 16KB | Ps 32KB = 96KB.
// ---------------------------------------------------------------------------
#define FLASH_SMEM 98304

__global__ __launch_bounds__(256, 2)
void flash_hmma(const float* __restrict__ Qg, const float* __restrict__ Kg,
                const float* __restrict__ Vg, const int* __restrict__ mask,
                float* __restrict__ O)
{
    extern __shared__ __align__(128) float sm[];
    const uint32_t sb = smem_u32(sm);
    const uint32_t QS = sb;
    const uint32_t KS = sb + 8192  * 4;
    const uint32_t VT = sb + 12288 * 4;
    const uint32_t PS = sb + 16384 * 4;

    const int tid  = threadIdx.x;
    const int lane = tid & 31;
    const int w    = tid >> 5;
    const int m0   = blockIdx.x * 128;
    const int h    = blockIdx.y;
    const int b    = blockIdx.z;

    // ---- load Q tile (scaled by 1/8, tf32-rounded), swizzled ----
    #pragma unroll
    for (int q = 0; q < 8; q++) {
        int id = tid + q * 256;
        int r  = id >> 4;
        int ch = id & 15;
        float4 v = *(const float4*)(Qg + ((size_t)(b*S_ + m0 + r) * H_ + h) * 64 + ch * 4);
        uint32_t x0 = f2tf32(v.x * 0.125f), x1 = f2tf32(v.y * 0.125f);
        uint32_t x2 = f2tf32(v.z * 0.125f), x3 = f2tf32(v.w * 0.125f);
        asm volatile("st.shared.v4.b32 [%0], {%1,%2,%3,%4};"
                     :: "r"(swz(QS, r, ch)), "r"(x0), "r"(x1), "r"(x2), "r"(x3) : "memory");
    }

    float o[8][4];
    #pragma unroll
    for (int nf = 0; nf < 8; nf++)
        #pragma unroll
        for (int e = 0; e < 4; e++) o[nf][e] = 0.f;
    float mi0 = -1e30f, mi1 = -1e30f, li0 = 0.f, li1 = 0.f;

    const int rl = lane >> 2;          // local row 0..7 (and +8)
    const int cb = (lane & 3) * 2;     // col pair base within n-frag

    for (int j0 = 0; j0 < S_; j0 += 64) {
        __syncthreads();
        // ---- load K (swizzled) and V (transposed, swizzled) ----
        #pragma unroll
        for (int q = 0; q < 4; q++) {
            int id = tid + q * 256;
            int t  = id & 63;
            int ch = id >> 6;          // 0..15
            size_t g = ((size_t)(b*S_ + j0 + t) * H_ + h) * 64 + ch * 4;
            float4 kv = *(const float4*)(Kg + g);
            uint32_t k0 = f2tf32(kv.x), k1 = f2tf32(kv.y), k2 = f2tf32(kv.z), k3 = f2tf32(kv.w);
            asm volatile("st.shared.v4.b32 [%0], {%1,%2,%3,%4};"
                         :: "r"(swz(KS, t, ch)), "r"(k0), "r"(k1), "r"(k2), "r"(k3) : "memory");
            float4 vv = *(const float4*)(Vg + g);
            uint32_t vr[4] = { f2tf32(vv.x), f2tf32(vv.y), f2tf32(vv.z), f2tf32(vv.w) };
            #pragma unroll
            for (int i = 0; i < 4; i++) {
                int vrow = ch * 4 + i;
                uint32_t ad = VT + vrow * 256 + ((uint32_t)((t >> 2) ^ (vrow & 7)) << 4)
                            + (t & 3) * 4;
                asm volatile("st.shared.b32 [%0], %1;" :: "r"(ad), "r"(vr[i]) : "memory");
            }
        }
        __syncthreads();

        // ---- scores: S = Q K^T  (16x64 per warp) ----
        float s[8][4];
        #pragma unroll
        for (int nf = 0; nf < 8; nf++)
            #pragma unroll
            for (int e = 0; e < 4; e++) s[nf][e] = 0.f;

        #pragma unroll
        for (int ks = 0; ks < 8; ks++) {
            uint32_t a0, a1, a2, a3;
            {
                int row = w * 16 + (lane & 7) + ((lane >> 3) & 1) * 8;
                int ch  = 2 * ks + (lane >> 4);
                ldsm_x4(a0, a1, a2, a3, swz(QS, row, ch));
            }
            #pragma unroll
            for (int i = 0; i < 4; i++) {
                int row = (lane & 7) + ((lane >> 4) << 3) + 16 * i;
                int ch  = 2 * ks + ((lane >> 3) & 1);
                uint32_t b0, b1, b2, b3;
                ldsm_x4(b0, b1, b2, b3, swz(KS, row, ch));
                mma_tf32(s[2*i],   a0, a1, a2, a3, b0, b1);
                mma_tf32(s[2*i+1], a0, a1, a2, a3, b2, b3);
            }
        }

        // ---- mask ----
        const int gr0 = m0 + w * 16 + rl;
        const int gr1 = gr0 + 8;
        #pragma unroll
        for (int nf = 0; nf < 8; nf++) {
            int col = j0 + nf * 8 + cb;
            int2 m0v = *(const int2*)(mask + ((size_t)b*S_ + gr0) * S_ + col);
            int2 m1v = *(const int2*)(mask + ((size_t)b*S_ + gr1) * S_ + col);
            if (m0v.x == 0) s[nf][0] = -1e10f;
            if (m0v.y == 0) s[nf][1] = -1e10f;
            if (m1v.x == 0) s[nf][2] = -1e10f;
            if (m1v.y == 0) s[nf][3] = -1e10f;
        }

        // ---- online softmax (warp-local; rows owned by quads) ----
        float mx0 = -1e30f, mx1 = -1e30f;
        #pragma unroll
        for (int nf = 0; nf < 8; nf++) {
            mx0 = fmaxf(mx0, fmaxf(s[nf][0], s[nf][1]));
            mx1 = fmaxf(mx1, fmaxf(s[nf][2], s[nf][3]));
        }
        #pragma unroll
        for (int off = 1; off <= 2; off <<= 1) {
            mx0 = fmaxf(mx0, __shfl_xor_sync(0xffffffffu, mx0, off));
            mx1 = fmaxf(mx1, __shfl_xor_sync(0xffffffffu, mx1, off));
        }
        float nm0 = fmaxf(mi0, mx0), nm1 = fmaxf(mi1, mx1);
        float c0 = __expf(mi0 - nm0), c1 = __expf(mi1 - nm1);
        mi0 = nm0; mi1 = nm1;

        float sum0 = 0.f, sum1 = 0.f;
        #pragma unroll
        for (int nf = 0; nf < 8; nf++) {
            s[nf][0] = __expf(s[nf][0] - nm0); sum0 += s[nf][0];
            s[nf][1] = __expf(s[nf][1] - nm0); sum0 += s[nf][1];
            s[nf][2] = __expf(s[nf][2] - nm1); sum1 += s[nf][2];
            s[nf][3] = __expf(s[nf][3] - nm1); sum1 += s[nf][3];
        }
        #pragma unroll
        for (int off = 1; off <= 2; off <<= 1) {
            sum0 += __shfl_xor_sync(0xffffffffu, sum0, off);
            sum1 += __shfl_xor_sync(0xffffffffu, sum1, off);
        }
        li0 = li0 * c0 + sum0;
        li1 = li1 * c1 + sum1;
        #pragma unroll
        for (int nf = 0; nf < 8; nf++) {
            o[nf][0] *= c0; o[nf][1] *= c0;
            o[nf][2] *= c1; o[nf][3] *= c1;
        }

        // ---- store P (tf32) to warp-private smem rows ----
        {
            const int pr0 = w * 16 + rl;
            const int pr8 = pr0 + 8;
            #pragma unroll
            for (int nf = 0; nf < 8; nf++) {
                int col   = nf * 8 + cb;
                int chunk = col >> 2;
                int cin   = (col & 3) * 4;
                uint32_t ad0 = PS + pr0 * 256 + ((uint32_t)(chunk ^ (pr0 & 7)) << 4) + cin;
                uint32_t ad1 = PS + pr8 * 256 + ((uint32_t)(chunk ^ (pr8 & 7)) << 4) + cin;
                uint32_t p0 = f2tf32(s[nf][0]), p1 = f2tf32(s[nf][1]);
                uint32_t p2 = f2tf32(s[nf][2]), p3 = f2tf32(s[nf][3]);
                asm volatile("st.shared.v2.b32 [%0], {%1,%2};" :: "r"(ad0), "r"(p0), "r"(p1) : "memory");
                asm volatile("st.shared.v2.b32 [%0], {%1,%2};" :: "r"(ad1), "r"(p2), "r"(p3) : "memory");
            }
        }
        __syncwarp();

        // ---- O += P @ V ----
        #pragma unroll
        for (int ks = 0; ks < 8; ks++) {
            uint32_t a0, a1, a2, a3;
            {
                int row = w * 16 + (lane & 7) + ((lane >> 3) & 1) * 8;
                int ch  = 2 * ks + (lane >> 4);
                ldsm_x4(a0, a1, a2, a3, swz(PS, row, ch));
            }
            #pragma unroll
            for (int i = 0; i < 4; i++) {
                int row = (lane & 7) + ((lane >> 4) << 3) + 16 * i;
                int ch  = 2 * ks + ((lane >> 3) & 1);
                uint32_t b0, b1, b2, b3;
                ldsm_x4(b0, b1, b2, b3, swz(VT, row, ch));
                mma_tf32(o[2*i],   a0, a1, a2, a3, b0, b1);
                mma_tf32(o[2*i+1], a0, a1, a2, a3, b2, b3);
            }
        }
    }

    // ---- epilogue ----
    {
        float i0 = 1.f / li0, i1 = 1.f / li1;
        const int gr0 = m0 + w * 16 + rl;
        const int gr1 = gr0 + 8;
        #pragma unroll
        for (int nf = 0; nf < 8; nf++) {
            int col = nf * 8 + cb;
            *(float2*)(O + ((size_t)(b*S_ + gr0) * H_ + h) * 64 + col)
                = make_float2(o[nf][0] * i0, o[nf][1] * i0);
            *(float2*)(O + ((size_t)(b*S_ + gr1) * H_ + h) * 64 + col)
                = make_float2(o[nf][2] * i1, o[nf][3] * i1);
        }
    }
}

// ---------------------------------------------------------------------------
// Launch
// ---------------------------------------------------------------------------
extern "C" void kernel_launch(void* const* d_in, const int* in_sizes, int n_in,
                              void* d_out, int out_size)
{
    const float* queries = (const float*)d_in[0];
    const float* keys    = (const float*)d_in[1];
    const float* values  = (const float*)d_in[2];
    const int*   mask    = (const int*  )d_in[3];
    const float* Wq      = (const float*)d_in[4];
    const float* Wk      = (const float*)d_in[5];
    const float* Wv      = (const float*)d_in[6];
    const float* Wo      = (const float*)d_in[7];
    float* out = (float*)d_out;

    float *q, *k, *v, *ao;
    cudaGetSymbolAddress((void**)&q,  g_q);
    cudaGetSymbolAddress((void**)&k,  g_k);
    cudaGetSymbolAddress((void**)&v,  g_v);
    cudaGetSymbolAddress((void**)&ao, g_ao);

    const int M = B_ * S_;        // 8192
    const int N = H_ * DK_;       // 1024

    cudaFuncSetAttribute(gemm_hmma, cudaFuncAttributeMaxDynamicSharedMemorySize, GEMM_SMEM);
    cudaFuncSetAttribute(flash_hmma, cudaFuncAttributeMaxDynamicSharedMemorySize, FLASH_SMEM);

    dim3 gg(N / 128, M / 128);    // (8, 64)
    gemm_hmma<<<gg, 256, GEMM_SMEM>>>(queries, Wq, q, M, N, D_);
    gemm_hmma<<<gg, 256, GEMM_SMEM>>>(keys,    Wk, k, M, N, D_);
    gemm_hmma<<<gg, 256, GEMM_SMEM>>>(values,  Wv, v, M, N, D_);

    dim3 gf(S_ / 128, H_, B_);    // (16, 16, 4)
    flash_hmma<<<gf, 256, FLASH_SMEM>>>(q, k, v, mask, ao);

    dim3 go(D_ / 128, M / 128);
    gemm_hmma<<<go, 256, GEMM_SMEM>>>(ao, Wo, out, M, D_, H_*DV_);
}